// round 16
// baseline (speedup 1.0000x reference)
#include <cuda_runtime.h>
#include <math.h>

typedef unsigned long long u64;
typedef unsigned int u32;

#define NTH 384
#define NW 12
#define GRID 148

// ---- smem word offsets ----
// per-MLP block: W1T[64c][12] = 768 | b1 f32[64] | W2T[64c][68] = 4352 |
//                b2 f32[64] | W3 f32[64][DOUT] | b3 f32[DOUT]
#define MLP_S 0
#define MLP_A 5316
#define MLP_F 10632
#define MLP_R 15948
#define AS_OFF 21392
#define FS_OFF 24848
#define HS_OFF 28304
#define SMEM_WORDS 54416
#define SMEM_BYTES (SMEM_WORDS * 4)   // 217664 B

struct KParams {
    const float* in[30];
    float* out;
    int B;
};

// ---------------- helpers ----------------
__device__ __forceinline__ u32 f2tf(float x) {
    u32 r; asm("cvt.rna.tf32.f32 %0, %1;" : "=r"(r) : "f"(x)); return r;
}
__device__ __forceinline__ float tanh_hw(float x) {
    float r; asm("tanh.approx.f32 %0, %1;" : "=f"(r) : "f"(x)); return r;
}
__device__ __forceinline__ float tanh_exact(float x) {
    float ax = fabsf(x);
    float e  = __expf(2.0f * ax);
    float t  = 1.0f - __fdividef(2.0f, e + 1.0f);
    return (x < 0.0f) ? -t : t;
}
__device__ __forceinline__ float softplusf(float x) {
    float t = __expf(-fabsf(x));
    return fmaxf(x, 0.0f) + __logf(1.0f + t);
}
// m16n8k8 tf32 MMA, D = A*B + D
__device__ __forceinline__ void mma8(float& c0, float& c1, float& c2, float& c3,
                                     u32 a0, u32 a1, u32 a2, u32 a3, u32 b0, u32 b1) {
    asm("mma.sync.aligned.m16n8k8.row.col.f32.tf32.tf32.f32 "
        "{%0,%1,%2,%3}, {%4,%5,%6,%7}, {%8,%9}, {%0,%1,%2,%3};"
        : "+f"(c0), "+f"(c1), "+f"(c2), "+f"(c3)
        : "r"(a0), "r"(a1), "r"(a2), "r"(a3), "r"(b0), "r"(b1));
}

// One MLP (8->64 tanh -> 64 tanh -> DOUT) for 32 rows, warp-cooperative.
// B fragments loaded ONCE per (n,k) and reused for both 16-row tiles.
template <int DOUT>
__device__ __forceinline__ void run_mlp_mma(
    const u32* __restrict__ wb, const u32* __restrict__ As, u32* __restrict__ Hs,
    int g, int ti, float (&y)[2][2][DOUT])
{
    const float* B1  = (const float*)(wb + 768);
    const u32*   W2T = wb + 832;
    const float* B2  = (const float*)(wb + 5184);
    const float* W3  = (const float*)(wb + 5248);
    const float* B3  = W3 + 64 * DOUT;

    // ---- layer 1: [32x8] @ [8x64]; B fragments shared across tiles ----
    {
        u32 a[2][4];
#pragma unroll
        for (int t = 0; t < 2; t++) {
            a[t][0] = As[(t*16 + g)     * 9 + ti];
            a[t][1] = As[(t*16 + g + 8) * 9 + ti];
            a[t][2] = As[(t*16 + g)     * 9 + ti + 4];
            a[t][3] = As[(t*16 + g + 8) * 9 + ti + 4];
        }
#pragma unroll
        for (int n = 0; n < 8; n++) {
            u32 b0 = wb[(n*8 + g)*12 + ti];
            u32 b1 = wb[(n*8 + g)*12 + ti + 4];
            float bb0 = B1[n*8 + 2*ti], bb1 = B1[n*8 + 2*ti + 1];
#pragma unroll
            for (int t = 0; t < 2; t++) {
                float c0 = bb0, c1 = bb1, c2 = bb0, c3 = bb1;
                mma8(c0, c1, c2, c3, a[t][0], a[t][1], a[t][2], a[t][3], b0, b1);
                u32 h0 = f2tf(tanh_hw(c0)), h1 = f2tf(tanh_hw(c1));
                u32 h2 = f2tf(tanh_hw(c2)), h3 = f2tf(tanh_hw(c3));
                int r0 = (t*16 + g)     * 68 + n*8 + 2*ti;
                int r1 = (t*16 + g + 8) * 68 + n*8 + 2*ti;
                *(u64*)(Hs + r0) = (u64)h0 | ((u64)h1 << 32);
                *(u64*)(Hs + r1) = (u64)h2 | ((u64)h3 << 32);
            }
        }
    }
    __syncwarp();

    // ---- layer 2: [32x64] @ [64x64] + streaming layer 3; B shared ----
    {
        u32 A0[2][8], A1[2][8], A2[2][8], A3[2][8];
#pragma unroll
        for (int t = 0; t < 2; t++)
#pragma unroll
            for (int k = 0; k < 8; k++) {
                int b0i = (t*16 + g)     * 68 + k*8;
                int b1i = (t*16 + g + 8) * 68 + k*8;
                A0[t][k] = Hs[b0i + ti];  A2[t][k] = Hs[b0i + ti + 4];
                A1[t][k] = Hs[b1i + ti];  A3[t][k] = Hs[b1i + ti + 4];
            }
        float p0[2][DOUT], p1[2][DOUT];
#pragma unroll
        for (int t = 0; t < 2; t++)
#pragma unroll
            for (int o = 0; o < DOUT; o++) { p0[t][o] = 0.0f; p1[t][o] = 0.0f; }

#pragma unroll
        for (int n = 0; n < 8; n++) {
            float bb0 = B2[n*8 + 2*ti], bb1 = B2[n*8 + 2*ti + 1];
            float c00 = bb0, c01 = bb1, c02 = bb0, c03 = bb1;
            float c10 = bb0, c11 = bb1, c12 = bb0, c13 = bb1;
#pragma unroll
            for (int k = 0; k < 8; k++) {
                u32 b0 = W2T[(n*8 + g)*68 + k*8 + ti];
                u32 b1 = W2T[(n*8 + g)*68 + k*8 + ti + 4];
                mma8(c00, c01, c02, c03, A0[0][k], A1[0][k], A2[0][k], A3[0][k], b0, b1);
                mma8(c10, c11, c12, c13, A0[1][k], A1[1][k], A2[1][k], A3[1][k], b0, b1);
            }
            float t00 = tanh_hw(c00), t01 = tanh_hw(c01), t02 = tanh_hw(c02), t03 = tanh_hw(c03);
            float t10 = tanh_hw(c10), t11 = tanh_hw(c11), t12 = tanh_hw(c12), t13 = tanh_hw(c13);
#pragma unroll
            for (int o = 0; o < DOUT; o++) {
                float w0 = W3[(n*8 + 2*ti)     * DOUT + o];
                float w1 = W3[(n*8 + 2*ti + 1) * DOUT + o];
                p0[0][o] += t00 * w0 + t01 * w1;
                p1[0][o] += t02 * w0 + t03 * w1;
                p0[1][o] += t10 * w0 + t11 * w1;
                p1[1][o] += t12 * w0 + t13 * w1;
            }
        }
#pragma unroll
        for (int t = 0; t < 2; t++)
#pragma unroll
            for (int o = 0; o < DOUT; o++) {
                float a0 = p0[t][o], a1 = p1[t][o];
                a0 += __shfl_xor_sync(0xffffffffu, a0, 1);
                a0 += __shfl_xor_sync(0xffffffffu, a0, 2);
                a1 += __shfl_xor_sync(0xffffffffu, a1, 1);
                a1 += __shfl_xor_sync(0xffffffffu, a1, 2);
                y[t][0][o] = a0 + B3[o];
                y[t][1][o] = a1 + B3[o];
            }
    }
    __syncwarp();
}

extern __shared__ u32 smu[];

__global__ void __launch_bounds__(NTH, 1)
fused_mlp_kernel(KParams p)
{
    float* smf = (float*)smu;
    const int tid = threadIdx.x;

    const int DINs[4]  = {7, 7, 6, 5};
    const int DOUTs[4] = {1, 1, 1, 3};
    const int WOFF[4]  = {MLP_S, MLP_A, MLP_F, MLP_R};
    for (int m = 0; m < 4; m++) {
        const float* W1 = p.in[6 + m*6 + 0];
        const float* B1 = p.in[6 + m*6 + 1];
        const float* W2 = p.in[6 + m*6 + 2];
        const float* B2 = p.in[6 + m*6 + 3];
        const float* W3 = p.in[6 + m*6 + 4];
        const float* B3 = p.in[6 + m*6 + 5];
        int base = WOFF[m], din = DINs[m], dout = DOUTs[m];
        for (int i = tid; i < 768; i += NTH) {
            int c = i / 12, r = i % 12;
            smu[base + i] = (r < din) ? f2tf(W1[r*64 + c]) : 0u;
        }
        for (int i = tid; i < 64; i += NTH) smf[base + 768 + i] = B1[i];
        for (int i = tid; i < 4352; i += NTH) {
            int c = i / 68, r = i % 68;
            smu[base + 832 + i] = (r < 64) ? f2tf(W2[r*64 + c]) : 0u;
        }
        for (int i = tid; i < 64; i += NTH)      smf[base + 5184 + i] = B2[i];
        for (int i = tid; i < 64*dout; i += NTH) smf[base + 5248 + i] = W3[i];
        for (int i = tid; i < dout; i += NTH)    smf[base + 5248 + 64*dout + i] = B3[i];
    }
    __syncthreads();

    const float im0 = p.in[2][0], im1 = p.in[2][1], im2 = p.in[2][2], im3 = p.in[2][3], im4 = p.in[2][4];
    const float is0 = p.in[3][0], is1 = p.in[3][1], is2 = p.in[3][2], is3 = p.in[3][3], is4 = p.in[3][4];
    const float tm0 = p.in[4][0], tm1 = p.in[4][1], tm2 = p.in[4][2];
    const float ts0 = p.in[5][0], ts1 = p.in[5][1], ts2 = p.in[5][2];

    const int w = tid >> 5, lane = tid & 31, g = lane >> 2, ti = lane & 3;
    u32*   As = smu + AS_OFF + w * 288;
    float* Fs = smf + FS_OFF + w * 288;
    u32*   Hs = smu + HS_OFF + w * 2176;

    const float* xd0 = p.in[0];
    const float* utr = p.in[1];
    const int B = p.B;
    const int ntasks = (B + 31) >> 5;

    for (int task = blockIdx.x * NW + w; task < ntasks; task += GRID * NW) {
        __syncwarp();
        const int row = task * 32 + lane;
        const int rc  = min(row, B - 1);

        float vx    = __fdividef(xd0[rc*3 + 0] - im0, is0);
        float vy    = __fdividef(xd0[rc*3 + 1] - im1, is1);
        float wz    = __fdividef(xd0[rc*3 + 2] - im2, is2);
        float vel   = __fdividef(utr[rc*2 + 0] - im3, is3);
        float delta = __fdividef(utr[rc*2 + 1] - im4, is4);
        float vmag  = sqrtf(fmaf(vx, vx, fmaf(vy, vy, 1e-8f)));
        float vsg   = (vx > 0.0f) ? 1.0f : ((vx < 0.0f) ? -1.0f : 0.0f);

        Fs[lane*9 + 0] = vx; Fs[lane*9 + 1] = vy; Fs[lane*9 + 2] = wz;
        Fs[lane*9 + 3] = vel; Fs[lane*9 + 4] = delta;

        // ---- steer MLP: [delta, vel, vx, vy, w, mag, sign, 0] ----
        As[lane*9 + 0] = f2tf(delta); As[lane*9 + 1] = f2tf(vel);
        As[lane*9 + 2] = f2tf(vx);    As[lane*9 + 3] = f2tf(vy);
        As[lane*9 + 4] = f2tf(wz);    As[lane*9 + 5] = f2tf(vmag);
        As[lane*9 + 6] = f2tf(vsg);   As[lane*9 + 7] = 0u;
        __syncwarp();
        float ys_[2][2][1];
        run_mlp_mma<1>(smu + MLP_S, As, Hs, g, ti, ys_);

        // ---- acc MLP: [vel, delta, vx, mag, sign, vy, w, 0] ----
        As[lane*9 + 0] = f2tf(vel);  As[lane*9 + 1] = f2tf(delta);
        As[lane*9 + 2] = f2tf(vx);   As[lane*9 + 3] = f2tf(vmag);
        As[lane*9 + 4] = f2tf(vsg);  As[lane*9 + 5] = f2tf(vy);
        As[lane*9 + 6] = f2tf(wz);   As[lane*9 + 7] = 0u;
        __syncwarp();
        float ya_[2][2][1];
        run_mlp_mma<1>(smu + MLP_A, As, Hs, g, ti, ya_);

        // ---- ue per lane's 4 rows; ti==0 lane publishes to Fs ----
#pragma unroll
        for (int t = 0; t < 2; t++)
#pragma unroll
            for (int j = 0; j < 2; j++) {
                int lr = t*16 + g + j*8;
                float velr   = Fs[lr*9 + 3];
                float deltar = Fs[lr*9 + 4];
                float u0 = velr   + 0.5f * tanh_exact(ya_[t][j][0]);
                float u1 = deltar + 0.5f * tanh_exact(ys_[t][j][0]);
                if (ti == 0) { Fs[lr*9 + 5] = u0; Fs[lr*9 + 6] = u1; }
            }
        __syncwarp();

        // ---- ut_eff_raw store (row-owner, coalesced float2) ----
        {
            float u0 = fmaf(Fs[lane*9 + 5], is3, im3);
            float u1 = fmaf(Fs[lane*9 + 6], is4, im4);
            if (row < B) ((float2*)p.out)[row] = make_float2(u0, u1);
        }

        // ---- friction MLP: [vx, vy, w, ue0, ue1, DT, 0, 0] ----
        As[lane*9 + 0] = f2tf(Fs[lane*9 + 0]); As[lane*9 + 1] = f2tf(Fs[lane*9 + 1]);
        As[lane*9 + 2] = f2tf(Fs[lane*9 + 2]); As[lane*9 + 3] = f2tf(Fs[lane*9 + 5]);
        As[lane*9 + 4] = f2tf(Fs[lane*9 + 6]); As[lane*9 + 5] = f2tf(0.02f);
        As[lane*9 + 6] = 0u;                   As[lane*9 + 7] = 0u;
        __syncwarp();
        float yf_[2][2][1];
        run_mlp_mma<1>(smu + MLP_F, As, Hs, g, ti, yf_);
        if (ti == 0) {
#pragma unroll
            for (int t = 0; t < 2; t++)
#pragma unroll
                for (int j = 0; j < 2; j++) {
                    int rr = task*32 + t*16 + g + j*8;
                    if (rr < B) p.out[2*B + rr] = 1.0f + softplusf(yf_[t][j][0]);
                }
        }

        // ---- residual MLP: [vx, vy, w, ue0, ue1, 0, 0, 0] ----
        As[lane*9 + 0] = f2tf(Fs[lane*9 + 0]); As[lane*9 + 1] = f2tf(Fs[lane*9 + 1]);
        As[lane*9 + 2] = f2tf(Fs[lane*9 + 2]); As[lane*9 + 3] = f2tf(Fs[lane*9 + 5]);
        As[lane*9 + 4] = f2tf(Fs[lane*9 + 6]); As[lane*9 + 5] = 0u;
        As[lane*9 + 6] = 0u;                   As[lane*9 + 7] = 0u;
        __syncwarp();
        float yr_[2][2][3];
        run_mlp_mma<3>(smu + MLP_R, As, Hs, g, ti, yr_);
        if (ti == 0) {
#pragma unroll
            for (int t = 0; t < 2; t++)
#pragma unroll
                for (int j = 0; j < 2; j++) {
                    int rr = task*32 + t*16 + g + j*8;
                    if (rr < B) {
                        p.out[3*B + rr*3 + 0] = fmaf(yr_[t][j][0], ts0, tm0);
                        p.out[3*B + rr*3 + 1] = fmaf(yr_[t][j][1], ts1, tm1);
                        p.out[3*B + rr*3 + 2] = fmaf(yr_[t][j][2], ts2, tm2);
                    }
                }
        }
    }
}

extern "C" void kernel_launch(void* const* d_in, const int* in_sizes, int n_in,
                              void* d_out, int out_size)
{
    KParams p;
    for (int i = 0; i < 30; i++) p.in[i] = (const float*)d_in[i];
    p.out = (float*)d_out;
    p.B = in_sizes[0] / 3;

    cudaFuncSetAttribute(fused_mlp_kernel,
                         cudaFuncAttributeMaxDynamicSharedMemorySize, SMEM_BYTES);
    fused_mlp_kernel<<<GRID, NTH, SMEM_BYTES>>>(p);
}

// round 17
// speedup vs baseline: 1.7361x; 1.7361x over previous
#include <cuda_runtime.h>
#include <math.h>

typedef unsigned long long u64;
typedef unsigned int u32;

#define NTH 512
#define NW 16
#define GRID 148

// ---- smem word offsets ----
// per-MLP block: W1H[64c][12w] f16x2 = 768 | b1 f32[64] | W2H[64c][36w] f16x2 = 2304 |
//                b2 f32[64] | W3 f32[64][DOUT] | b3 f32[DOUT]
//   W1H[c*12+w] = half2(W1[2w][c], W1[2w+1][c])  (w<4; rows>=din -> 0)
//   W2H[c*36+w] = half2(W2[2w][c], W2[2w+1][c])  (w<32)
#define MLP_S 0
#define MLP_A 3268
#define MLP_F 6536
#define MLP_R 9804
#define AS_OFF 13200    // 16 warps x 384 words ([32 rows][12] f16x2, words 0..3 used)
#define FS_OFF 19344    // 16 x 288 ([32][9] f32)
#define HS_OFF 23952    // 16 x 1152 ([32 rows][36] f16x2)
#define SMEM_WORDS 42384
#define SMEM_BYTES (SMEM_WORDS * 4)   // 169536 B

struct KParams {
    const float* in[30];
    float* out;
    int B;
};

// ---------------- helpers ----------------
// pack two f32 -> f16x2 (lo in low half, hi in high half)
__device__ __forceinline__ u32 f2h2(float lo, float hi) {
    u32 r; asm("cvt.rn.f16x2.f32 %0, %1, %2;" : "=r"(r) : "f"(hi), "f"(lo)); return r;
}
__device__ __forceinline__ float tanh_hw(float x) {
    float r; asm("tanh.approx.f32 %0, %1;" : "=f"(r) : "f"(x)); return r;
}
__device__ __forceinline__ float tanh_exact(float x) {
    float ax = fabsf(x);
    float e  = __expf(2.0f * ax);
    float t  = 1.0f - __fdividef(2.0f, e + 1.0f);
    return (x < 0.0f) ? -t : t;
}
__device__ __forceinline__ float softplusf(float x) {
    float t = __expf(-fabsf(x));
    return fmaxf(x, 0.0f) + __logf(1.0f + t);
}
// m16n8k16 f16 MMA, f32 accum, D = A*B + D
__device__ __forceinline__ void mma16(float& c0, float& c1, float& c2, float& c3,
                                      u32 a0, u32 a1, u32 a2, u32 a3, u32 b0, u32 b1) {
    asm("mma.sync.aligned.m16n8k16.row.col.f32.f16.f16.f32 "
        "{%0,%1,%2,%3}, {%4,%5,%6,%7}, {%8,%9}, {%0,%1,%2,%3};"
        : "+f"(c0), "+f"(c1), "+f"(c2), "+f"(c3)
        : "r"(a0), "r"(a1), "r"(a2), "r"(a3), "r"(b0), "r"(b1));
}

// One MLP (8->64 tanh -> 64 tanh -> DOUT) for 32 rows, warp-cooperative, fp16 MMA.
template <int DOUT>
__device__ __forceinline__ void run_mlp_mma(
    const u32* __restrict__ wb, const u32* __restrict__ As, u32* __restrict__ Hs,
    int g, int ti, float (&y)[2][2][DOUT])
{
    const float* B1  = (const float*)(wb + 768);
    const u32*   W2H = wb + 832;
    const float* B2  = (const float*)(wb + 3136);
    const float* W3  = (const float*)(wb + 3200);
    const float* B3  = W3 + 64 * DOUT;

    // ---- layer 1: [32x8(pad16)] @ [8x64]; K fits one MMA (upper half zero) ----
    {
        u32 a0[2], a1[2];
#pragma unroll
        for (int t = 0; t < 2; t++) {
            a0[t] = As[(t*16 + g)     * 12 + ti];
            a1[t] = As[(t*16 + g + 8) * 12 + ti];
        }
#pragma unroll
        for (int n = 0; n < 8; n++) {
            u32 b0 = wb[(n*8 + g)*12 + ti];
            float bb0 = B1[n*8 + 2*ti], bb1 = B1[n*8 + 2*ti + 1];
#pragma unroll
            for (int t = 0; t < 2; t++) {
                float c0 = bb0, c1 = bb1, c2 = bb0, c3 = bb1;
                mma16(c0, c1, c2, c3, a0[t], a1[t], 0u, 0u, b0, 0u);
                Hs[(t*16 + g)     * 36 + n*4 + ti] = f2h2(tanh_hw(c0), tanh_hw(c1));
                Hs[(t*16 + g + 8) * 36 + n*4 + ti] = f2h2(tanh_hw(c2), tanh_hw(c3));
            }
        }
    }
    __syncwarp();

    // ---- layer 2: [32x64] @ [64x64] in 4 K=16 steps + streaming layer 3 ----
    {
        u32 A0[2][4], A1[2][4], A2[2][4], A3[2][4];
#pragma unroll
        for (int t = 0; t < 2; t++)
#pragma unroll
            for (int s = 0; s < 4; s++) {
                int r0 = (t*16 + g)     * 36 + s*8;
                int r1 = (t*16 + g + 8) * 36 + s*8;
                A0[t][s] = Hs[r0 + ti];     A1[t][s] = Hs[r1 + ti];
                A2[t][s] = Hs[r0 + ti + 4]; A3[t][s] = Hs[r1 + ti + 4];
            }
        float p0[2][DOUT], p1[2][DOUT];
#pragma unroll
        for (int t = 0; t < 2; t++)
#pragma unroll
            for (int o = 0; o < DOUT; o++) { p0[t][o] = 0.0f; p1[t][o] = 0.0f; }

#pragma unroll
        for (int n = 0; n < 8; n++) {
            float bb0 = B2[n*8 + 2*ti], bb1 = B2[n*8 + 2*ti + 1];
            float c00 = bb0, c01 = bb1, c02 = bb0, c03 = bb1;
            float c10 = bb0, c11 = bb1, c12 = bb0, c13 = bb1;
#pragma unroll
            for (int s = 0; s < 4; s++) {
                u32 b0 = W2H[(n*8 + g)*36 + s*8 + ti];
                u32 b1 = W2H[(n*8 + g)*36 + s*8 + ti + 4];
                mma16(c00, c01, c02, c03, A0[0][s], A1[0][s], A2[0][s], A3[0][s], b0, b1);
                mma16(c10, c11, c12, c13, A0[1][s], A1[1][s], A2[1][s], A3[1][s], b0, b1);
            }
            float t00 = tanh_hw(c00), t01 = tanh_hw(c01), t02 = tanh_hw(c02), t03 = tanh_hw(c03);
            float t10 = tanh_hw(c10), t11 = tanh_hw(c11), t12 = tanh_hw(c12), t13 = tanh_hw(c13);
#pragma unroll
            for (int o = 0; o < DOUT; o++) {
                float w0 = W3[(n*8 + 2*ti)     * DOUT + o];
                float w1 = W3[(n*8 + 2*ti + 1) * DOUT + o];
                p0[0][o] += t00 * w0 + t01 * w1;
                p1[0][o] += t02 * w0 + t03 * w1;
                p0[1][o] += t10 * w0 + t11 * w1;
                p1[1][o] += t12 * w0 + t13 * w1;
            }
        }
#pragma unroll
        for (int t = 0; t < 2; t++)
#pragma unroll
            for (int o = 0; o < DOUT; o++) {
                float a0 = p0[t][o], a1 = p1[t][o];
                a0 += __shfl_xor_sync(0xffffffffu, a0, 1);
                a0 += __shfl_xor_sync(0xffffffffu, a0, 2);
                a1 += __shfl_xor_sync(0xffffffffu, a1, 1);
                a1 += __shfl_xor_sync(0xffffffffu, a1, 2);
                y[t][0][o] = a0 + B3[o];
                y[t][1][o] = a1 + B3[o];
            }
    }
    __syncwarp();
}

extern __shared__ u32 smu[];

__global__ void __launch_bounds__(NTH, 1)
fused_mlp_kernel(KParams p)
{
    float* smf = (float*)smu;
    const int tid = threadIdx.x;

    // ---- stage weights: fp16x2 packed, transposed, padded strides ----
    const int DINs[4]  = {7, 7, 6, 5};
    const int DOUTs[4] = {1, 1, 1, 3};
    const int WOFF[4]  = {MLP_S, MLP_A, MLP_F, MLP_R};
    for (int m = 0; m < 4; m++) {
        const float* W1 = p.in[6 + m*6 + 0];
        const float* B1 = p.in[6 + m*6 + 1];
        const float* W2 = p.in[6 + m*6 + 2];
        const float* B2 = p.in[6 + m*6 + 3];
        const float* W3 = p.in[6 + m*6 + 4];
        const float* B3 = p.in[6 + m*6 + 5];
        int base = WOFF[m], din = DINs[m], dout = DOUTs[m];
        for (int i = tid; i < 768; i += NTH) {
            int c = i / 12, w = i % 12;
            u32 v = 0u;
            if (w < 4) {
                int r0 = 2*w, r1 = 2*w + 1;
                float lo = (r0 < din) ? W1[r0*64 + c] : 0.0f;
                float hi = (r1 < din) ? W1[r1*64 + c] : 0.0f;
                v = f2h2(lo, hi);
            }
            smu[base + i] = v;
        }
        for (int i = tid; i < 64; i += NTH) smf[base + 768 + i] = B1[i];
        for (int i = tid; i < 2304; i += NTH) {
            int c = i / 36, w = i % 36;
            u32 v = 0u;
            if (w < 32) v = f2h2(W2[(2*w)*64 + c], W2[(2*w + 1)*64 + c]);
            smu[base + 832 + i] = v;
        }
        for (int i = tid; i < 64; i += NTH)      smf[base + 3136 + i] = B2[i];
        for (int i = tid; i < 64*dout; i += NTH) smf[base + 3200 + i] = W3[i];
        for (int i = tid; i < dout; i += NTH)    smf[base + 3200 + 64*dout + i] = B3[i];
    }
    __syncthreads();

    const float im0 = p.in[2][0], im1 = p.in[2][1], im2 = p.in[2][2], im3 = p.in[2][3], im4 = p.in[2][4];
    const float is0 = p.in[3][0], is1 = p.in[3][1], is2 = p.in[3][2], is3 = p.in[3][3], is4 = p.in[3][4];
    const float tm0 = p.in[4][0], tm1 = p.in[4][1], tm2 = p.in[4][2];
    const float ts0 = p.in[5][0], ts1 = p.in[5][1], ts2 = p.in[5][2];

    const int w = tid >> 5, lane = tid & 31, g = lane >> 2, ti = lane & 3;
    u32*   As = smu + AS_OFF + w * 384;
    float* Fs = smf + FS_OFF + w * 288;
    u32*   Hs = smu + HS_OFF + w * 1152;

    const float* xd0 = p.in[0];
    const float* utr = p.in[1];
    const int B = p.B;
    const int ntasks = (B + 31) >> 5;

    for (int task = blockIdx.x * NW + w; task < ntasks; task += GRID * NW) {
        __syncwarp();
        const int row = task * 32 + lane;
        const int rc  = min(row, B - 1);

        float vx    = __fdividef(xd0[rc*3 + 0] - im0, is0);
        float vy    = __fdividef(xd0[rc*3 + 1] - im1, is1);
        float wz    = __fdividef(xd0[rc*3 + 2] - im2, is2);
        float vel   = __fdividef(utr[rc*2 + 0] - im3, is3);
        float delta = __fdividef(utr[rc*2 + 1] - im4, is4);
        float vmag  = sqrtf(fmaf(vx, vx, fmaf(vy, vy, 1e-8f)));
        float vsg   = (vx > 0.0f) ? 1.0f : ((vx < 0.0f) ? -1.0f : 0.0f);

        Fs[lane*9 + 0] = vx; Fs[lane*9 + 1] = vy; Fs[lane*9 + 2] = wz;
        Fs[lane*9 + 3] = vel; Fs[lane*9 + 4] = delta;

        // ---- steer MLP: [delta, vel, vx, vy, w, mag, sign, 0] ----
        As[lane*12 + 0] = f2h2(delta, vel);
        As[lane*12 + 1] = f2h2(vx, vy);
        As[lane*12 + 2] = f2h2(wz, vmag);
        As[lane*12 + 3] = f2h2(vsg, 0.0f);
        __syncwarp();
        float ys_[2][2][1];
        run_mlp_mma<1>(smu + MLP_S, As, Hs, g, ti, ys_);

        // ---- acc MLP: [vel, delta, vx, mag, sign, vy, w, 0] ----
        As[lane*12 + 0] = f2h2(vel, delta);
        As[lane*12 + 1] = f2h2(vx, vmag);
        As[lane*12 + 2] = f2h2(vsg, vy);
        As[lane*12 + 3] = f2h2(wz, 0.0f);
        __syncwarp();
        float ya_[2][2][1];
        run_mlp_mma<1>(smu + MLP_A, As, Hs, g, ti, ya_);

        // ---- ue per lane's 4 rows; ti==0 lane publishes to Fs ----
#pragma unroll
        for (int t = 0; t < 2; t++)
#pragma unroll
            for (int j = 0; j < 2; j++) {
                int lr = t*16 + g + j*8;
                float velr   = Fs[lr*9 + 3];
                float deltar = Fs[lr*9 + 4];
                float u0 = velr   + 0.5f * tanh_exact(ya_[t][j][0]);
                float u1 = deltar + 0.5f * tanh_exact(ys_[t][j][0]);
                if (ti == 0) { Fs[lr*9 + 5] = u0; Fs[lr*9 + 6] = u1; }
            }
        __syncwarp();

        // ---- ut_eff_raw store (row-owner, coalesced float2) ----
        {
            float u0 = fmaf(Fs[lane*9 + 5], is3, im3);
            float u1 = fmaf(Fs[lane*9 + 6], is4, im4);
            if (row < B) ((float2*)p.out)[row] = make_float2(u0, u1);
        }

        // ---- friction MLP: [vx, vy, w, ue0, ue1, DT, 0, 0] ----
        As[lane*12 + 0] = f2h2(Fs[lane*9 + 0], Fs[lane*9 + 1]);
        As[lane*12 + 1] = f2h2(Fs[lane*9 + 2], Fs[lane*9 + 5]);
        As[lane*12 + 2] = f2h2(Fs[lane*9 + 6], 0.02f);
        As[lane*12 + 3] = 0u;
        __syncwarp();
        float yf_[2][2][1];
        run_mlp_mma<1>(smu + MLP_F, As, Hs, g, ti, yf_);
        if (ti == 0) {
#pragma unroll
            for (int t = 0; t < 2; t++)
#pragma unroll
                for (int j = 0; j < 2; j++) {
                    int rr = task*32 + t*16 + g + j*8;
                    if (rr < B) p.out[2*B + rr] = 1.0f + softplusf(yf_[t][j][0]);
                }
        }

        // ---- residual MLP: [vx, vy, w, ue0, ue1, 0, 0, 0] ----
        As[lane*12 + 0] = f2h2(Fs[lane*9 + 0], Fs[lane*9 + 1]);
        As[lane*12 + 1] = f2h2(Fs[lane*9 + 2], Fs[lane*9 + 5]);
        As[lane*12 + 2] = f2h2(Fs[lane*9 + 6], 0.0f);
        As[lane*12 + 3] = 0u;
        __syncwarp();
        float yr_[2][2][3];
        run_mlp_mma<3>(smu + MLP_R, As, Hs, g, ti, yr_);
        if (ti == 0) {
#pragma unroll
            for (int t = 0; t < 2; t++)
#pragma unroll
                for (int j = 0; j < 2; j++) {
                    int rr = task*32 + t*16 + g + j*8;
                    if (rr < B) {
                        p.out[3*B + rr*3 + 0] = fmaf(yr_[t][j][0], ts0, tm0);
                        p.out[3*B + rr*3 + 1] = fmaf(yr_[t][j][1], ts1, tm1);
                        p.out[3*B + rr*3 + 2] = fmaf(yr_[t][j][2], ts2, tm2);
                    }
                }
        }
    }
}

extern "C" void kernel_launch(void* const* d_in, const int* in_sizes, int n_in,
                              void* d_out, int out_size)
{
    KParams p;
    for (int i = 0; i < 30; i++) p.in[i] = (const float*)d_in[i];
    p.out = (float*)d_out;
    p.B = in_sizes[0] / 3;

    cudaFuncSetAttribute(fused_mlp_kernel,
                         cudaFuncAttributeMaxDynamicSharedMemorySize, SMEM_BYTES);
    fused_mlp_kernel<<<GRID, NTH, SMEM_BYTES>>>(p);
}